// round 17
// baseline (speedup 1.0000x reference)
#include <cuda_runtime.h>
#include <cstdint>

// ---------------- problem constants ----------------
#define N_ROWS 16384
#define KC 8192
#define D 256
#define LOSS_OFF 4194304
#define IDX_OFF 4194305
#define QCAP (1 << 20)
#define NTPC 4

typedef unsigned long long u64;

// ---------------- device scratch ----------------
__device__ uint2 g_A8[(size_t)N_ROWS * 32];   // x int8 [m][256]
__device__ uint2 g_B8[(size_t)KC * 32];       // e int8 [n][256]
__device__ float g_Axf[(size_t)N_ROWS * D];   // x fp32 row-major (exact recheck)
__device__ float g_en2[KC];
__device__ float g_xn2[N_ROWS];
__device__ float g_invsx[N_ROWS];
__device__ float g_invse[KC];
__device__ int g_maxen = 0;
__device__ int g_maxive = 0;
__device__ u64 g_part[(size_t)N_ROWS * 64];   // packed [d1|idx13|dq19]
__device__ int g_idx[N_ROWS];                 // fast idx or -1 -> g_best
__device__ u64 g_best[N_ROWS];
__device__ int g_queue[QCAP];                 // tasks: (row<<13)|k
__device__ int g_qn;

// ---------------- helpers ----------------
__device__ __forceinline__ uint32_t smem_u32(const void* p) {
    uint32_t a;
    asm("{ .reg .u64 t; cvta.to.shared.u64 t, %1; cvt.u32.u64 %0, t; }" : "=r"(a) : "l"(p));
    return a;
}
__device__ __forceinline__ u64 packdi(float d, int idx) {
    uint32_t u = __float_as_uint(d);
    u = (u & 0x80000000u) ? ~u : (u | 0x80000000u);
    return ((u64)u << 32) | (uint32_t)idx;
}
__device__ __forceinline__ float unpackd(u64 p) {
    uint32_t u = (uint32_t)(p >> 32);
    u = (u & 0x80000000u) ? (u ^ 0x80000000u) : ~u;
    return __uint_as_float(u);
}
__device__ __forceinline__ float dec_delta(u64 p) {
    return __uint_as_float(((uint32_t)(p & 0x7FFFFu)) << 13);
}
__device__ __forceinline__ void cpasync16(uint32_t sdst, const void* gsrc) {
    asm volatile("cp.async.cg.shared.global [%0], [%1], 16;" :: "r"(sdst), "l"(gsrc));
}
__device__ __forceinline__ void ldmx4(uint32_t addr, uint32_t& r0, uint32_t& r1,
                                      uint32_t& r2, uint32_t& r3) {
    asm volatile("ldmatrix.sync.aligned.m8n8.x4.shared.b16 {%0,%1,%2,%3}, [%4];"
                 : "=r"(r0), "=r"(r1), "=r"(r2), "=r"(r3) : "r"(addr));
}
__device__ __forceinline__ void mma16832i(int* c, const uint32_t* a, const uint32_t* b) {
    asm volatile(
        "mma.sync.aligned.m16n8k32.row.col.s32.s8.s8.s32 "
        "{%0,%1,%2,%3}, {%4,%5,%6,%7}, {%8,%9}, {%0,%1,%2,%3};"
        : "+r"(c[0]), "+r"(c[1]), "+r"(c[2]), "+r"(c[3])
        : "r"(a[0]), "r"(a[1]), "r"(a[2]), "r"(a[3]), "r"(b[0]), "r"(b[1]));
}
__device__ __forceinline__ uint32_t pack4i8(float a, float b, float c, float d, float s) {
    int q0 = (int)rintf(a * s), q1 = (int)rintf(b * s);
    int q2 = (int)rintf(c * s), q3 = (int)rintf(d * s);
    return (q0 & 255) | ((q1 & 255) << 8) | ((q2 & 255) << 16) | ((q3 & 255) << 24);
}

// ---------------- prepE ----------------
__global__ void prepE_kernel(const float* __restrict__ E, float* out) {
    int k = blockIdx.x * 8 + (threadIdx.x >> 5);
    int lane = threadIdx.x & 31;
    if (blockIdx.x == 0 && threadIdx.x == 0) { out[LOSS_OFF] = 0.0f; g_qn = 0; }
    const float4* p = (const float4*)(E + (size_t)k * D);
    float4 v0 = p[lane * 2], v1 = p[lane * 2 + 1];
    float s = v0.x*v0.x + v0.y*v0.y + v0.z*v0.z + v0.w*v0.w
            + v1.x*v1.x + v1.y*v1.y + v1.z*v1.z + v1.w*v1.w;
    float mx = fmaxf(fmaxf(fmaxf(fabsf(v0.x), fabsf(v0.y)), fmaxf(fabsf(v0.z), fabsf(v0.w))),
                     fmaxf(fmaxf(fabsf(v1.x), fabsf(v1.y)), fmaxf(fabsf(v1.z), fabsf(v1.w))));
    #pragma unroll
    for (int o = 16; o > 0; o >>= 1) {
        s += __shfl_xor_sync(0xffffffffu, s, o);
        mx = fmaxf(mx, __shfl_xor_sync(0xffffffffu, mx, o));
    }
    float scale = 126.0f / mx;
    float inv = mx * (1.0f / 126.0f);
    uint2 q;
    q.x = pack4i8(v0.x, v0.y, v0.z, v0.w, scale);
    q.y = pack4i8(v1.x, v1.y, v1.z, v1.w, scale);
    g_B8[(size_t)k * 32 + lane] = q;
    if (lane == 0) {
        g_en2[k] = s;
        g_invse[k] = inv;
        atomicMax(&g_maxen, __float_as_int(s));
        atomicMax(&g_maxive, __float_as_int(inv));
    }
}

// ---------------- prepA ----------------
__global__ void prepA_kernel(const float* __restrict__ hs) {
    __shared__ float tile[32][33];
    __shared__ float snorm[8][32];
    __shared__ float smax[8][32];
    __shared__ float sScale[32];
    int m0 = blockIdx.x * 32, b = m0 >> 10, p0 = m0 & 1023;
    int tx = threadIdx.x, ty = threadIdx.y;
    float nacc = 0.0f, macc = 0.0f;
    for (int cc = 0; cc < 8; cc++) {
        int c0 = cc * 32;
        __syncthreads();
        #pragma unroll
        for (int i = 0; i < 4; i++) {
            int c = c0 + ty + i * 8;
            float v = hs[((size_t)(b * 256 + c)) * 1024 + p0 + tx];
            tile[ty + i * 8][tx] = v;
            nacc = fmaf(v, v, nacc);
            macc = fmaxf(macc, fabsf(v));
        }
        __syncthreads();
        #pragma unroll
        for (int i = 0; i < 4; i++) {
            int row = ty + i * 8;
            g_Axf[(size_t)(m0 + row) * D + c0 + tx] = tile[tx][row];
        }
    }
    snorm[ty][tx] = nacc;
    smax[ty][tx] = macc;
    __syncthreads();
    if (ty == 0) {
        float tot = 0.0f, mx = 0.0f;
        #pragma unroll
        for (int j = 0; j < 8; j++) { tot += snorm[j][tx]; mx = fmaxf(mx, smax[j][tx]); }
        g_xn2[m0 + tx] = tot;
        float scale = 126.0f / mx;
        g_invsx[m0 + tx] = mx * (1.0f / 126.0f);
        sScale[tx] = scale;
    }
    __syncthreads();
    int tid = ty * 32 + tx;
    #pragma unroll
    for (int i = 0; i < 4; i++) {
        int t = tid + i * 256;
        int r = t >> 5, seg = t & 31;
        const float4* src = (const float4*)(g_Axf + (size_t)(m0 + r) * D + seg * 8);
        float4 a = src[0], c = src[1];
        float s = sScale[r];
        uint2 q;
        q.x = pack4i8(a.x, a.y, a.z, a.w, s);
        q.y = pack4i8(c.x, c.y, c.z, c.w, s);
        g_A8[(size_t)(m0 + r) * 32 + seg] = q;
    }
}

// ---------------- main GEMM: A-resident CTA over NTPC ntiles -----------------------
#define SA_OFF    0
#define SB_OFF(b) (32768 + (b) * 16384)
#define SEN_OFF   65536
#define SIV_OFF   66048
#define SIX_OFF   66560
#define SPART_OFF 67072
#define SMEM_SZ   (1024 + 67072 + 4096)

__global__ void __launch_bounds__(256, 2)
gemm_kernel() {
    extern __shared__ char smem_raw[];
    char* base = (char*)(((uintptr_t)smem_raw + 1023) & ~(uintptr_t)1023);
    uint32_t sb = smem_u32(base);
    float* sEn = (float*)(base + SEN_OFF);
    float* sIv = (float*)(base + SIV_OFF);
    float* sIx = (float*)(base + SIX_OFF);
    u64* sPart = (u64*)(base + SPART_OFF);

    const int tid = threadIdx.x;
    const int lane = tid & 31, wid = tid >> 5;
    const int wm = wid & 3, wn = wid >> 2;
    const int ntg = blockIdx.x, mtile = blockIdx.y;
    const int m0 = mtile * 128;

    if (tid < 128) sIx[tid] = g_invsx[m0 + tid];

    // load A: both K-chunks, resident for whole kernel
    #pragma unroll
    for (int c = 0; c < 2; c++)
        #pragma unroll
        for (int it = 0; it < 4; it++) {
            int idx = tid + it * 256;
            int row = idx >> 3, kg = idx & 7;
            uint32_t soff = row * 128 + (((uint32_t)(kg ^ (row & 7))) << 4);
            cpasync16(sb + SA_OFF + c * 16384 + soff,
                      (const char*)g_A8 + (size_t)(m0 + row) * 256 + c * 128 + kg * 16);
        }
    asm volatile("cp.async.commit_group;");

    auto load_b = [&](int g, int bf) {
        int nt = g >> 1, c = g & 1;
        int n0g = (ntg * NTPC + nt) * 128;
        #pragma unroll
        for (int it = 0; it < 4; it++) {
            int idx = tid + it * 256;
            int row = idx >> 3, kg = idx & 7;
            uint32_t soff = row * 128 + (((uint32_t)(kg ^ (row & 7))) << 4);
            cpasync16(sb + SB_OFF(bf) + soff,
                      (const char*)g_B8 + (size_t)(n0g + row) * 256 + c * 128 + kg * 16);
        }
        asm volatile("cp.async.commit_group;");
    };

    load_b(0, 0);

    int acc[2][8][4];
    #pragma unroll
    for (int mt = 0; mt < 2; mt++)
        #pragma unroll
        for (int nt = 0; nt < 8; nt++)
            #pragma unroll
            for (int q = 0; q < 4; q++) acc[mt][nt][q] = 0;

    for (int g = 0; g < 2 * NTPC; g++) {
        int nt = g >> 1, c = g & 1;
        int n0 = (ntg * NTPC + nt) * 128;
        if (c == 0 && tid < 128) {           // prev epilogue done (loop-end sync)
            sEn[tid] = g_en2[n0 + tid];
            sIv[tid] = g_invse[n0 + tid];
        }
        if (g + 1 < 2 * NTPC) {
            load_b(g + 1, (g + 1) & 1);
            asm volatile("cp.async.wait_group 1;" ::: "memory");
        } else {
            asm volatile("cp.async.wait_group 0;" ::: "memory");
        }
        __syncthreads();

        uint32_t ab = sb + SA_OFF + c * 16384, bbse = sb + SB_OFF(g & 1);
        #pragma unroll
        for (int ks = 0; ks < 4; ks++) {
            uint32_t a[2][4], bb[8][2];
            uint32_t kg = ks * 2 + (lane >> 4);
            uint32_t kx = ((kg ^ (lane & 7)) << 4);
            #pragma unroll
            for (int mt = 0; mt < 2; mt++) {
                uint32_t row = wm * 32 + mt * 16 + (lane & 15);
                ldmx4(ab + row * 128 + kx, a[mt][0], a[mt][1], a[mt][2], a[mt][3]);
            }
            #pragma unroll
            for (int nt2 = 0; nt2 < 4; nt2++) {
                uint32_t row = wn * 64 + nt2 * 16 + (lane & 15);
                uint32_t r0, r1, r2, r3;
                ldmx4(bbse + row * 128 + kx, r0, r1, r2, r3);
                bb[nt2 * 2][0] = r0; bb[nt2 * 2][1] = r2;
                bb[nt2 * 2 + 1][0] = r1; bb[nt2 * 2 + 1][1] = r3;
            }
            #pragma unroll
            for (int mt = 0; mt < 2; mt++)
                #pragma unroll
                for (int nt2 = 0; nt2 < 8; nt2++)
                    mma16832i(acc[mt][nt2], a[mt], bb[nt2]);
        }

        if (c == 1) {
            // epilogue for ntile = ntg*NTPC + nt
            int ntile = ntg * NTPC + nt;
            #pragma unroll
            for (int mt = 0; mt < 2; mt++) {
                #pragma unroll
                for (int half = 0; half < 2; half++) {
                    int rl = wm * 32 + mt * 16 + half * 8 + (lane >> 2);
                    float m2ivx = -2.0f * sIx[rl];
                    u64 t1 = ~0ull, t2 = ~0ull;
                    #pragma unroll
                    for (int nt2 = 0; nt2 < 8; nt2++) {
                        #pragma unroll
                        for (int cc = 0; cc < 2; cc++) {
                            int col = wn * 64 + nt2 * 8 + (lane & 3) * 2 + cc;
                            float dist = fmaf((float)acc[mt][nt2][half * 2 + cc],
                                              m2ivx * sIv[col], sEn[col]);
                            u64 pk = packdi(dist, n0 + col);
                            if (pk < t1) { t2 = t1; t1 = pk; }
                            else if (pk < t2) { t2 = pk; }
                        }
                    }
                    #pragma unroll
                    for (int dlt = 1; dlt <= 2; dlt <<= 1) {
                        u64 o1 = __shfl_xor_sync(0xffffffffu, t1, dlt);
                        u64 o2 = __shfl_xor_sync(0xffffffffu, t2, dlt);
                        u64 n1 = min(t1, o1);
                        u64 n2 = min(max(t1, o1), min(t2, o2));
                        t1 = n1; t2 = n2;
                    }
                    if ((lane & 3) == 0) {
                        sPart[rl * 4 + wn * 2] = t1;
                        sPart[rl * 4 + wn * 2 + 1] = t2;
                    }
                }
            }
            __syncthreads();
            if (tid < 128) {
                u64 p1 = ~0ull, p2 = ~0ull;
                #pragma unroll
                for (int w = 0; w < 2; w++) {
                    u64 a1 = sPart[tid * 4 + w * 2], a2 = sPart[tid * 4 + w * 2 + 1];
                    u64 n1 = min(p1, a1);
                    u64 n2 = min(max(p1, a1), min(p2, a2));
                    p1 = n1; p2 = n2;
                }
                float d1 = unpackd(p1), d2 = unpackd(p2);
                uint32_t dq = __float_as_uint(fmaxf(d2 - d1, 0.0f)) >> 13;
                u64 packed = ((p1 >> 32) << 32)
                           | (((p1 & 0xFFFFFFFFull) & 0x1FFFull) << 19)
                           | (u64)(dq & 0x7FFFFu);
                g_part[(size_t)(m0 + tid) * 64 + ntile] = packed;
            }
            // zero accumulators for next ntile
            #pragma unroll
            for (int mt = 0; mt < 2; mt++)
                #pragma unroll
                for (int nt2 = 0; nt2 < 8; nt2++)
                    #pragma unroll
                    for (int q = 0; q < 4; q++) acc[mt][nt2][q] = 0;
        }
        __syncthreads();
    }
}

// ---------------- merge_fast: 4 rows per warp ----------------------------------------
__global__ void merge_fast_kernel(float* __restrict__ out) {
    int wid = threadIdx.x >> 5, lane = threadIdx.x & 31;
    int rbase = blockIdx.x * 32 + wid * 4;
    float ive = __int_as_float(g_maxive);

    #pragma unroll
    for (int i = 0; i < 4; i++) {
        int row = rbase + i;
        const ulonglong2* pp = (const ulonglong2*)(g_part + (size_t)row * 64);
        ulonglong2 ee = pp[lane];

        u64 m = min(ee.x, ee.y);
        #pragma unroll
        for (int o = 16; o > 0; o >>= 1) m = min(m, __shfl_xor_sync(0xffffffffu, m, o));

        float ivx = __ldg(&g_invsx[row]);
        float pad = 5.2f * sqrtf(ivx * ivx * __int_as_float(g_maxen)
                                 + ive * ive * __ldg(&g_xn2[row])) + 0.1f;
        float thr = unpackd(m) + pad;

        float d10 = unpackd(ee.x), d11 = unpackd(ee.y);
        float d20 = d10 + dec_delta(ee.x), d21 = d11 + dec_delta(ee.y);
        bool f0 = d20 <= thr, f1 = d21 <= thr;
        bool c0 = (!f0) && (d10 <= thr);
        bool c1 = (!f1) && (d11 <= thr);
        unsigned mf = __ballot_sync(0xffffffffu, f0 | f1);
        int nc = (int)c0 + (int)c1;
        #pragma unroll
        for (int o = 16; o > 0; o >>= 1) nc += __shfl_xor_sync(0xffffffffu, nc, o);

        if (mf == 0 && nc == 1) {
            if (lane == 0) {
                int k = (int)((m >> 19) & 0x1FFFu);
                g_idx[row] = k;
            }
            continue;
        }

        if (lane == 0) { g_best[row] = ~0ull; g_idx[row] = -1; }
        int rsh = row << 13;
        if (c0) {
            int q = atomicAdd(&g_qn, 1);
            if (q < QCAP) g_queue[q] = rsh | (int)((ee.x >> 19) & 0x1FFFu);
        }
        if (c1) {
            int q = atomicAdd(&g_qn, 1);
            if (q < QCAP) g_queue[q] = rsh | (int)((ee.y >> 19) & 0x1FFFu);
        }
        if (f0) {
            int q = atomicAdd(&g_qn, 128);
            int k0 = (lane * 2) * 128;
            for (int j = 0; j < 128 && q + j < QCAP; j++) g_queue[q + j] = rsh | (k0 + j);
        }
        if (f1) {
            int q = atomicAdd(&g_qn, 128);
            int k0 = (lane * 2 + 1) * 128;
            for (int j = 0; j < 128 && q + j < QCAP; j++) g_queue[q + j] = rsh | (k0 + j);
        }
    }
}

// ---------------- merge_slow: one warp per candidate task ---------------------------
__global__ void __launch_bounds__(256, 8)
merge_slow_kernel(const float* __restrict__ E) {
    int nt = g_qn;
    if (nt > QCAP) nt = QCAP;
    int lane = threadIdx.x & 31;
    int gw = (blockIdx.x * 256 + threadIdx.x) >> 5;
    int nwarp = (gridDim.x * 256) >> 5;

    for (int t = gw; t < nt; t += nwarp) {
        int task = g_queue[t];
        int row = task >> 13, k = task & 0x1FFF;
        const float* xr = g_Axf + (size_t)row * D;
        const float* ek = E + (size_t)k * D;
        float s = 0.0f;
        #pragma unroll
        for (int j = 0; j < 8; j++)
            s = fmaf(__ldg(xr + lane + j * 32), __ldg(ek + lane + j * 32), s);
        #pragma unroll
        for (int o = 16; o > 0; o >>= 1) s += __shfl_xor_sync(0xffffffffu, s, o);
        if (lane == 0) {
            float dist = fmaf(-2.0f, s, __ldg(&g_en2[k]));
            atomicMin(&g_best[row], packdi(dist, k));
        }
    }
}

// ---------------- final: resolves slow rows, writes idx + quant + loss --------------
__global__ void __launch_bounds__(256, 4)
final_kernel(const float* __restrict__ hs, const float* __restrict__ E,
             float* __restrict__ out) {
    __shared__ int sIdx[32];
    __shared__ float sE[32 * 257];
    __shared__ float sRed[8];
    int tid = threadIdx.x, lane = tid & 31, wid = tid >> 5;
    int row0 = blockIdx.x * 32;
    int b = row0 >> 10, p0 = row0 & 1023;
    size_t xbase = (size_t)b * 256 * 1024 + p0;

    if (tid < 32) {
        int k = g_idx[row0 + tid];
        if (k < 0) k = (int)(g_best[row0 + tid] & 0xFFFFFFFFu);
        sIdx[tid] = k;
        out[IDX_OFF + row0 + tid] = (float)k;
    }
    __syncthreads();

    #pragma unroll
    for (int j = 0; j < 4; j++) {
        int r = wid * 4 + j;
        const float* ek = E + (size_t)sIdx[r] * D;
        #pragma unroll
        for (int q = 0; q < 8; q++)
            sE[r * 257 + q * 32 + lane] = __ldg(ek + q * 32 + lane);
    }
    __syncthreads();

    float lsum = 0.0f;
    const float* sEr = sE + lane * 257;
    #pragma unroll 4
    for (int i = 0; i < 32; i++) {
        int c = wid + 8 * i;
        size_t ad = xbase + (size_t)c * 1024 + lane;
        float xv = hs[ad];
        float ev = sEr[c];
        out[ad] = ev;
        float d = ev - xv;
        lsum = fmaf(d, d, lsum);
    }
    #pragma unroll
    for (int o = 16; o > 0; o >>= 1) lsum += __shfl_xor_sync(0xffffffffu, lsum, o);
    if (lane == 0) sRed[wid] = lsum;
    __syncthreads();
    if (tid == 0) {
        float tot = 0.0f;
        #pragma unroll
        for (int w = 0; w < 8; w++) tot += sRed[w];
        atomicAdd(out + LOSS_OFF, tot * (1.25f / 4194304.0f));
    }
}

extern "C" void kernel_launch(void* const* d_in, const int* in_sizes, int n_in,
                              void* d_out, int out_size) {
    const float* hs = (const float*)d_in[0];
    const float* E  = (const float*)d_in[1];
    float* out = (float*)d_out;

    cudaFuncSetAttribute(gemm_kernel,
                         cudaFuncAttributeMaxDynamicSharedMemorySize, SMEM_SZ);

    prepE_kernel<<<KC / 8, 256>>>(E, out);
    prepA_kernel<<<N_ROWS / 32, dim3(32, 8)>>>(hs);
    gemm_kernel<<<dim3(KC / 128 / NTPC, N_ROWS / 128), 256, SMEM_SZ>>>();
    merge_fast_kernel<<<N_ROWS / 32, 256>>>(out);
    merge_slow_kernel<<<592, 256>>>(E);
    final_kernel<<<N_ROWS / 32, 256>>>(hs, E, out);
}